// round 9
// baseline (speedup 1.0000x reference)
#include <cuda_runtime.h>

// Problem constants (fixed by the dataset)
#define BB 4
#define NN 40960
#define KK 16
#define DOUT 16
#define BN_EPS 1e-5f

// Scratch: xyz padded to float4 so each neighbor gather is a single LDG.128.
// B*N = 163840 float4 = 2.62 MB. __device__ global => allocation-free.
__device__ float4 g_xyz4[BB * NN];

// --- Kernel 1: pack xyz [B,N,3] f32 -> float4 scratch, 4 points/thread ----
__global__ void pack_xyz_kernel(const float4* __restrict__ xyz4) {
    int i = blockIdx.x * blockDim.x + threadIdx.x;   // 0 .. B*N/4-1
    if (i < BB * NN / 4) {
        float4 a = xyz4[3 * i + 0];   // x0 y0 z0 x1
        float4 b = xyz4[3 * i + 1];   // y1 z1 x2 y2
        float4 c = xyz4[3 * i + 2];   // z2 x3 y3 z3
        float4* o = g_xyz4 + 4 * i;
        o[0] = make_float4(a.x, a.y, a.z, 0.0f);
        o[1] = make_float4(a.w, b.x, b.y, 0.0f);
        o[2] = make_float4(b.z, b.w, c.x, 0.0f);
        o[3] = make_float4(c.y, c.z, c.w, 0.0f);
    }
}

// --- Kernel 2: fused gather + encode + conv1x1 + BN + ReLU, 2-way pipelined
// Thread handles TWO units: (b, n, k0) and (b+2, n, k0). All 8 random gathers
// + 2 idx loads batched up front -> ~192 outstanding gathers/SM (was 128).
// NO reg cap (R7: capping regs serialized loads and regressed 36->50us).
__global__ __launch_bounds__(256) void lse_kernel(
    const int* __restrict__ idx,         // [B,N,K] int32
    const float* __restrict__ W,         // [DOUT,10]
    const float* __restrict__ gamma,
    const float* __restrict__ beta,
    const float* __restrict__ rmean,
    const float* __restrict__ rvar,
    float* __restrict__ out)             // [B,DOUT,N,K]
{
    // Per-block prepped weights: y[o] = bias + w0*dist + A.tile + Bm.neigh
    __shared__ float sW0[DOUT];
    __shared__ float sA[DOUT][3];
    __shared__ float sBm[DOUT][3];
    __shared__ float sBias[DOUT];

    int t = threadIdx.x;
    if (t < DOUT) {
        float inv_std = rsqrtf(rvar[t] + BN_EPS);
        float sc = gamma[t] * inv_std;
        const float* w = W + t * 10;
        sW0[t] = w[0] * sc;
#pragma unroll
        for (int c = 0; c < 3; c++) {
            float wr = w[1 + c], wt = w[4 + c], wn = w[7 + c];
            sA[t][c]  = (wr + wt) * sc;   // coefficient of tile (center xyz)
            sBm[t][c] = (wn - wr) * sc;   // coefficient of neighbor xyz
        }
        sBias[t] = beta[t] - gamma[t] * rmean[t] * inv_std;
    }
    __syncthreads();

    // gid in [0, B*N*K/8): covers b in {0,1}; partner unit is b+2.
    int gid = blockIdx.x * blockDim.x + t;
    int b = gid / (NN * (KK / 4));                   // 0 or 1
    int r = gid - b * (NN * (KK / 4));
    int n = r >> 2;
    int k0 = (r & 3) << 2;                           // 0,4,8,12

    // ---- batched loads for BOTH units ----
    const int* ipA = idx + (b * NN + n) * KK + k0;
    const int4 ivA = *(const int4*)(ipA);
    const int4 ivB = *(const int4*)(ipA + 2 * NN * KK);

    const float4* xbA = g_xyz4 + b * NN;
    const float4* xbB = xbA + 2 * NN;
    float4 tileA = xbA[n];
    float4 tileB = xbB[n];

    float4 a0 = xbA[ivA.x];
    float4 a1 = xbA[ivA.y];
    float4 a2 = xbA[ivA.z];
    float4 a3 = xbA[ivA.w];
    float4 c0 = xbB[ivB.x];
    float4 c1 = xbB[ivB.y];
    float4 c2 = xbB[ivB.z];
    float4 c3 = xbB[ivB.w];

    // ---- distances ----
    float axd = tileA.x - a0.x, ayd = tileA.y - a0.y, azd = tileA.z - a0.z;
    float dA0 = sqrtf(axd * axd + ayd * ayd + azd * azd);
    axd = tileA.x - a1.x; ayd = tileA.y - a1.y; azd = tileA.z - a1.z;
    float dA1 = sqrtf(axd * axd + ayd * ayd + azd * azd);
    axd = tileA.x - a2.x; ayd = tileA.y - a2.y; azd = tileA.z - a2.z;
    float dA2 = sqrtf(axd * axd + ayd * ayd + azd * azd);
    axd = tileA.x - a3.x; ayd = tileA.y - a3.y; azd = tileA.z - a3.z;
    float dA3 = sqrtf(axd * axd + ayd * ayd + azd * azd);

    axd = tileB.x - c0.x; ayd = tileB.y - c0.y; azd = tileB.z - c0.z;
    float dB0 = sqrtf(axd * axd + ayd * ayd + azd * azd);
    axd = tileB.x - c1.x; ayd = tileB.y - c1.y; azd = tileB.z - c1.z;
    float dB1 = sqrtf(axd * axd + ayd * ayd + azd * azd);
    axd = tileB.x - c2.x; ayd = tileB.y - c2.y; azd = tileB.z - c2.z;
    float dB2 = sqrtf(axd * axd + ayd * ayd + azd * azd);
    axd = tileB.x - c3.x; ayd = tileB.y - c3.y; azd = tileB.z - c3.z;
    float dB3 = sqrtf(axd * axd + ayd * ayd + azd * azd);

    // out[((b*16+o)*N + n)*K + k0] ; per-o stride = N*K; unit B offset fixed
    float* opA = out + (b * DOUT * NN + n) * KK + k0;
    float* opB = opA + 2 * DOUT * NN * KK;

#pragma unroll
    for (int o = 0; o < DOUT; o++) {
        float w0 = sW0[o];
        float q0 = sA[o][0], q1 = sA[o][1], q2 = sA[o][2];
        float m0 = sBm[o][0], m1 = sBm[o][1], m2 = sBm[o][2];
        float bias = sBias[o];

        float ttA = bias + q0 * tileA.x + q1 * tileA.y + q2 * tileA.z;
        float ttB = bias + q0 * tileB.x + q1 * tileB.y + q2 * tileB.z;

        float yA0 = ttA + w0 * dA0 + m0 * a0.x + m1 * a0.y + m2 * a0.z;
        float yA1 = ttA + w0 * dA1 + m0 * a1.x + m1 * a1.y + m2 * a1.z;
        float yA2 = ttA + w0 * dA2 + m0 * a2.x + m1 * a2.y + m2 * a2.z;
        float yA3 = ttA + w0 * dA3 + m0 * a3.x + m1 * a3.y + m2 * a3.z;
        *(float4*)(opA + o * (NN * KK)) =
            make_float4(fmaxf(yA0, 0.0f), fmaxf(yA1, 0.0f),
                        fmaxf(yA2, 0.0f), fmaxf(yA3, 0.0f));

        float yB0 = ttB + w0 * dB0 + m0 * c0.x + m1 * c0.y + m2 * c0.z;
        float yB1 = ttB + w0 * dB1 + m0 * c1.x + m1 * c1.y + m2 * c1.z;
        float yB2 = ttB + w0 * dB2 + m0 * c2.x + m1 * c2.y + m2 * c2.z;
        float yB3 = ttB + w0 * dB3 + m0 * c3.x + m1 * c3.y + m2 * c3.z;
        *(float4*)(opB + o * (NN * KK)) =
            make_float4(fmaxf(yB0, 0.0f), fmaxf(yB1, 0.0f),
                        fmaxf(yB2, 0.0f), fmaxf(yB3, 0.0f));
    }
}

extern "C" void kernel_launch(void* const* d_in, const int* in_sizes, int n_in,
                              void* d_out, int out_size) {
    // Bind inputs by element count (robust to metadata ordering).
    const float* xyz = 0;
    const int*   idx = 0;
    const float* W   = 0;
    const float* p16[4] = {0, 0, 0, 0};   // gamma, beta, rmean, rvar in order
    int n16 = 0;

    for (int i = 0; i < n_in; i++) {
        switch (in_sizes[i]) {
            case BB * NN * 3:        xyz = (const float*)d_in[i]; break;   // 491520
            case BB * NN * KK:       idx = (const int*)d_in[i];   break;   // 2621440
            case DOUT * 10:          W   = (const float*)d_in[i]; break;   // 160
            case DOUT:               if (n16 < 4) p16[n16++] = (const float*)d_in[i]; break;
            default: break;           // feature (1310720): unused
        }
    }
    const float* gamma = p16[0];
    const float* beta  = p16[1];
    const float* rmean = p16[2];
    const float* rvar  = p16[3];
    float* out = (float*)d_out;
    (void)out_size;

    const int pack_threads = BB * NN / 4;                 // 40960
    pack_xyz_kernel<<<(pack_threads + 255) / 256, 256>>>((const float4*)xyz);

    // Half the former grid: each thread does units (b,n,k0) and (b+2,n,k0).
    const int total = BB * NN * (KK / 4) / 2;             // 327680 threads
    lse_kernel<<<total / 256, 256>>>(idx, W, gamma, beta, rmean, rvar, out);
}